// round 3
// baseline (speedup 1.0000x reference)
#include <cuda_runtime.h>
#include <math.h>

#define BATCH   1024
#define D       64
#define NLEAVES 64
#define VOC     50000
#define NREL    7
#define KTOT    4224     // full (final): 4096 kron + 64 L-linear + 64 R-linear
#define SYMROWS 2304     // folded (compose): 2176 padded-triangular + 128 linear
#define LIN0    2176
#define PITCH   128      // SMEM pitch for transposed L/R tiles (M=128 per block)

// -------- device scratch (no runtime allocation allowed) --------
__device__ float g_vocT[VOC * D];
__device__ float g_XA[2 * BATCH * NLEAVES * D];
__device__ float g_XB[2 * BATCH * (NLEAVES / 2) * D];
__device__ float g_Wc[SYMROWS * D];
__device__ float g_Wf[KTOT * D];
__device__ float g_bc[D];
__device__ float g_bf[D];
__device__ float g_part[128 * 8192];                  // K-split partials (4 MB)

// packed fp32x2 ops (sm_103a; ptxas never emits FFMA2 from C++)
#define FMA2(d, a, b) asm("fma.rn.f32x2 %0, %1, %2, %0;" : "+l"(d) : "l"(a), "l"(b))
#define ADD2(d, a)    asm("add.rn.f32x2 %0, %0, %1;"      : "+l"(d) : "l"(a))
#define UNPK(lo, hi, v) asm("mov.b64 {%0,%1}, %2;" : "=f"(lo), "=f"(hi) : "l"(v))

#define FMA16(P)                                                                       \
    FMA2(P[0][0], a0.x, b0.x); FMA2(P[0][1], a0.x, b0.y); FMA2(P[0][2], a0.x, b1.x);   \
    FMA2(P[0][3], a0.x, b1.y);                                                         \
    FMA2(P[1][0], a0.y, b0.x); FMA2(P[1][1], a0.y, b0.y); FMA2(P[1][2], a0.y, b1.x);   \
    FMA2(P[1][3], a0.y, b1.y);                                                         \
    FMA2(P[2][0], a1.x, b0.x); FMA2(P[2][1], a1.x, b0.y); FMA2(P[2][2], a1.x, b1.x);   \
    FMA2(P[2][3], a1.x, b1.y);                                                         \
    FMA2(P[3][0], a1.y, b0.x); FMA2(P[3][1], a1.y, b0.y); FMA2(P[3][2], a1.y, b1.x);   \
    FMA2(P[3][3], a1.y, b1.y);

// triangular base row of chunk i (rows padded to multiple of 4)
__device__ __host__ __forceinline__ int tri_base(int i) {
    int a = i >> 2, b = i & 3;
    return 4 * (a + 1) * (2 * a + b);
}

// -------- vocab transpose: (64, 50000) -> (50000, 64) --------
__global__ void k_transpose_voc(const float* __restrict__ voc_w) {
    __shared__ float tile[64][65];
    int v0 = blockIdx.x * 64;
    for (int idx = threadIdx.x; idx < 64 * 64; idx += 256) {
        int d = idx >> 6, vv = idx & 63;
        int v = v0 + vv;
        tile[vv][d] = (v < VOC) ? voc_w[d * VOC + v] : 0.f;
    }
    __syncthreads();
    for (int idx = threadIdx.x; idx < 64 * 64; idx += 256) {
        int vv = idx >> 6, d = idx & 63;
        int v = v0 + vv;
        if (v < VOC) g_vocT[v * D + d] = tile[vv][d];
    }
}

// -------- weight prep --------
__global__ void k_prep(const float* __restrict__ cps_w,  const float* __restrict__ cps_b,
                       const float* __restrict__ cpst_w, const float* __restrict__ cpst_b,
                       const float* __restrict__ cpr_w,  const float* __restrict__ cpr_b,
                       const float* __restrict__ cprt_w, const float* __restrict__ cprt_b) {
    int blk = blockIdx.x;
    if (blk < 64) {
        int i = blk;
        int pad = (i + 4) & ~3;
        int base = tri_base(i);
        for (int idx = threadIdx.x; idx < pad * 64; idx += 256) {
            int j = idx >> 6, e = idx & 63;
            float v = 0.f;
            if (j < i)       v = cpst_w[e * 4096 + i * 64 + j] + cpst_w[e * 4096 + j * 64 + i];
            else if (j == i) v = cpst_w[e * 4096 + i * 65];
            g_Wc[(base + j) * 64 + e] = v;
        }
    } else if (blk == 64) {
        for (int idx = threadIdx.x; idx < 128 * 64; idx += 256) {
            int f = idx >> 6, e = idx & 63;
            g_Wc[(LIN0 + f) * 64 + e] = cps_w[e * 128 + f];
        }
        if (threadIdx.x < 64) {
            g_bc[threadIdx.x] = cps_b[threadIdx.x] + cpst_b[threadIdx.x];
            g_bf[threadIdx.x] = cpr_b[threadIdx.x] + cprt_b[threadIdx.x];
        }
    } else {
        int t = (blk - 65) * 256 + threadIdx.x;
        if (t < KTOT * D) {
            int e = t / KTOT, k = t % KTOT;
            float vf;
            if (k < 4096) vf = cprt_w[e * 4096 + k];
            else          vf = cpr_w[e * 128 + (k - 4096)];
            g_Wf[k * D + e] = vf;
        }
    }
}

// -------- embedding gather --------
__global__ void k_embed(const int* __restrict__ left, const int* __restrict__ right,
                        const float* __restrict__ voc_b) {
    int t = blockIdx.x * 256 + threadIdx.x;
    int node = t >> 4;
    int c = (t & 15) * 4;
    int tree = node >> 16;
    int bl = node & 0xFFFF;
    int idx = tree ? right[bl] : left[bl];
    float4 v  = *(const float4*)(g_vocT + idx * D + c);
    float4 bb = *(const float4*)(voc_b + c);
    v.x += bb.x; v.y += bb.y; v.z += bb.z; v.w += bb.w;
    *(float4*)(g_XA + node * D + c) = v;
}

// dup-store one float4 of W into Bs (b,b pairs for f32x2 operands)
__device__ __forceinline__ void bs_dup_store(float* Bs, int u, float4 w) {
    int j = u >> 4, eq = u & 15;
    float* dd = Bs + j * 128 + eq * 8;
    *(float4*)dd       = make_float4(w.x, w.x, w.y, w.y);
    *(float4*)(dd + 4) = make_float4(w.z, w.z, w.w, w.w);
}

// -------- one tree-compose level (symmetric-folded, f32x2, M=128 tile) --------
__global__ void __launch_bounds__(256, 2) k_compose(const float* __restrict__ Xin,
                                                    float* __restrict__ Xout,
                                                    float* __restrict__ part,
                                                    const float* __restrict__ W,
                                                    const float* __restrict__ bias,
                                                    int n_out, int split, int ntiles) {
    extern __shared__ float smem[];
    float* LsT = smem;                 // [64 f][128 m]
    float* RsT = smem + 64 * PITCH;
    float* Bs  = smem + 2 * 64 * PITCH;  // [rows][128] duplicated e-pairs
    const int t    = threadIdx.x;
    const int s    = blockIdx.x % split;
    const int tile = blockIdx.x / split;
    const int g0   = tile * 128;

    {   // load 128 pair-nodes (L||R contiguous), transpose into SMEM
        int m    = t >> 1;
        int half = t & 1;
        int g  = g0 + m;
        int p  = g % n_out;
        int bp = g / n_out;
        const float* src = Xin + (bp * 2 * n_out + 2 * p) * D + half * 64;
        float* dstT = (half ? RsT : LsT) + m;
#pragma unroll
        for (int it = 0; it < 16; it++) {
            int f = it * 4;
            float4 v = *(const float4*)(src + f);
            dstT[f * PITCH] = v.x; dstT[(f + 1) * PITCH] = v.y;
            dstT[(f + 2) * PITCH] = v.z; dstT[(f + 3) * PITCH] = v.w;
        }
    }

    const int tm = (t >> 4) * 8;   // 8 m per thread (4 packed pairs)
    const int te = (t & 15) * 4;   // 4 e per thread
    unsigned long long acc[4][4] = {};

    for (int c = s; c < 66; c += split) {
        int rows, base; const float* A; bool fold;
        if (c < 64) { rows = (c + 4) & ~3; base = tri_base(c); A = LsT; fold = true; }
        else { rows = 64; base = LIN0 + (c - 64) * 64; A = (c == 64) ? LsT : RsT; fold = false; }

        __syncthreads();
        {
            const float4* W4 = (const float4*)(W + base * 64);
            int n4 = rows * 16;
            for (int u = t; u < n4; u += 256) bs_dup_store(Bs, u, W4[u]);
        }
        __syncthreads();

        unsigned long long P[4][4] = {};
        const float* ap = A + tm;
        const float* bp = Bs + (te << 1);
#pragma unroll 4
        for (int j = 0; j < rows; j++) {
            ulonglong2 a0 = *(const ulonglong2*)ap;
            ulonglong2 a1 = *(const ulonglong2*)(ap + 4);
            ulonglong2 b0 = *(const ulonglong2*)bp;
            ulonglong2 b1 = *(const ulonglong2*)(bp + 4);
            FMA16(P)
            ap += PITCH; bp += 128;
        }
        if (fold) {
            ulonglong2 l0 = *(const ulonglong2*)(LsT + c * PITCH + tm);
            ulonglong2 l1 = *(const ulonglong2*)(LsT + c * PITCH + tm + 4);
            unsigned long long Lq[4] = {l0.x, l0.y, l1.x, l1.y};
#pragma unroll
            for (int q = 0; q < 4; q++)
#pragma unroll
                for (int nn = 0; nn < 4; nn++) FMA2(acc[q][nn], Lq[q], P[q][nn]);
        } else {
#pragma unroll
            for (int q = 0; q < 4; q++)
#pragma unroll
                for (int nn = 0; nn < 4; nn++) ADD2(acc[q][nn], P[q][nn]);
        }
    }

    if (split == 1) {
        float4 bv = *(const float4*)(bias + te);
        float bb[4] = {bv.x, bv.y, bv.z, bv.w};
#pragma unroll
        for (int q = 0; q < 4; q++) {
            float lo[4], hi[4];
#pragma unroll
            for (int nn = 0; nn < 4; nn++) UNPK(lo[nn], hi[nn], acc[q][nn]);
            int m0 = g0 + tm + 2 * q;
            float4 o0, o1;
            o0.x = tanhf(lo[0] + bb[0]); o0.y = tanhf(lo[1] + bb[1]);
            o0.z = tanhf(lo[2] + bb[2]); o0.w = tanhf(lo[3] + bb[3]);
            o1.x = tanhf(hi[0] + bb[0]); o1.y = tanhf(hi[1] + bb[1]);
            o1.z = tanhf(hi[2] + bb[2]); o1.w = tanhf(hi[3] + bb[3]);
            *(float4*)(Xout + (size_t)m0 * D + te)       = o0;
            *(float4*)(Xout + (size_t)(m0 + 1) * D + te) = o1;
        }
    } else {
        float* dst = part + (size_t)(s * ntiles + tile) * 8192;
#pragma unroll
        for (int q = 0; q < 4; q++) {
            float lo[4], hi[4];
#pragma unroll
            for (int nn = 0; nn < 4; nn++) UNPK(lo[nn], hi[nn], acc[q][nn]);
            int m0 = tm + 2 * q;
            *(float4*)(dst + m0 * 64 + te)       = make_float4(lo[0], lo[1], lo[2], lo[3]);
            *(float4*)(dst + (m0 + 1) * 64 + te) = make_float4(hi[0], hi[1], hi[2], hi[3]);
        }
    }
}

// -------- sum K-split partials + bias + tanh (tiles of 128 nodes) --------
__global__ void __launch_bounds__(256) k_reduce(const float* __restrict__ part,
                                                float* __restrict__ Xout,
                                                const float* __restrict__ bias,
                                                int ntiles, int split) {
    int tile = blockIdx.x;
    for (int idx = threadIdx.x; idx < 8192; idx += 256) {
        float sum = 0.f;
        for (int s = 0; s < split; s++) sum += part[(size_t)(s * ntiles + tile) * 8192 + idx];
        Xout[(size_t)tile * 8192 + idx] = tanhf(sum + bias[idx & 63]);
    }
}

// -------- final matmuls (asymmetric kron = l (x) r), f32x2, K-split --------
__global__ void __launch_bounds__(256, 2) k_final_part(const float* __restrict__ X,
                                                       float* __restrict__ part,
                                                       const float* __restrict__ W,
                                                       int split) {
    extern __shared__ float smem[];
    float* LsT = smem;
    float* RsT = smem + 64 * PITCH;
    float* Bs  = smem + 2 * 64 * PITCH;
    const int t    = threadIdx.x;
    const int s    = blockIdx.x % split;
    const int tile = blockIdx.x / split;
    const int g0   = tile * 128;

    {
        int m    = t >> 1;
        int half = t & 1;
        int b = g0 + m;
        const float* src = X + (size_t)(half ? (BATCH + b) : b) * D;
        float* dstT = (half ? RsT : LsT) + m;
#pragma unroll
        for (int it = 0; it < 16; it++) {
            int f = it * 4;
            float4 v = *(const float4*)(src + f);
            dstT[f * PITCH] = v.x; dstT[(f + 1) * PITCH] = v.y;
            dstT[(f + 2) * PITCH] = v.z; dstT[(f + 3) * PITCH] = v.w;
        }
    }

    const int tm = (t >> 4) * 8;
    const int te = (t & 15) * 4;
    unsigned long long acc[4][4] = {};

    for (int c = s; c < 66; c += split) {
        int base; const float* A; bool fold;
        if (c < 64) { base = c * 64; A = RsT; fold = true; }          // coeff = l_c
        else { base = 4096 + (c - 64) * 64; A = (c == 64) ? LsT : RsT; fold = false; }

        __syncthreads();
        {
            const float4* W4 = (const float4*)(W + base * 64);
            for (int u = t; u < 1024; u += 256) bs_dup_store(Bs, u, W4[u]);
        }
        __syncthreads();

        unsigned long long P[4][4] = {};
        const float* ap = A + tm;
        const float* bp = Bs + (te << 1);
#pragma unroll 4
        for (int j = 0; j < 64; j++) {
            ulonglong2 a0 = *(const ulonglong2*)ap;
            ulonglong2 a1 = *(const ulonglong2*)(ap + 4);
            ulonglong2 b0 = *(const ulonglong2*)bp;
            ulonglong2 b1 = *(const ulonglong2*)(bp + 4);
            FMA16(P)
            ap += PITCH; bp += 128;
        }
        if (fold) {
            ulonglong2 l0 = *(const ulonglong2*)(LsT + c * PITCH + tm);
            ulonglong2 l1 = *(const ulonglong2*)(LsT + c * PITCH + tm + 4);
            unsigned long long Lq[4] = {l0.x, l0.y, l1.x, l1.y};
#pragma unroll
            for (int q = 0; q < 4; q++)
#pragma unroll
                for (int nn = 0; nn < 4; nn++) FMA2(acc[q][nn], Lq[q], P[q][nn]);
        } else {
#pragma unroll
            for (int q = 0; q < 4; q++)
#pragma unroll
                for (int nn = 0; nn < 4; nn++) ADD2(acc[q][nn], P[q][nn]);
        }
    }

    float* dst = part + (size_t)(s * (BATCH / 128) + tile) * 8192;
#pragma unroll
    for (int q = 0; q < 4; q++) {
        float lo[4], hi[4];
#pragma unroll
        for (int nn = 0; nn < 4; nn++) UNPK(lo[nn], hi[nn], acc[q][nn]);
        int m0 = tm + 2 * q;
        *(float4*)(dst + m0 * 64 + te)       = make_float4(lo[0], lo[1], lo[2], lo[3]);
        *(float4*)(dst + (m0 + 1) * 64 + te) = make_float4(hi[0], hi[1], hi[2], hi[3]);
    }
}

// -------- final epilogue: reduce + bias + leaky + logits + softmax --------
__global__ void __launch_bounds__(256) k_final_reduce(const float* __restrict__ part,
                                                      float* __restrict__ out,
                                                      const float* __restrict__ bias,
                                                      const float* __restrict__ sm_w,
                                                      const float* __restrict__ sm_b,
                                                      int split) {
    __shared__ float actT[64 * 132];   // [e][m], pitch 132, 128 m per tile
    const int tile = blockIdx.x;       // BATCH/128 tiles
    const int t = threadIdx.x;
    const int ntiles = BATCH / 128;

    for (int idx = t; idx < 8192; idx += 256) {
        float sum = 0.f;
        for (int s = 0; s < split; s++) sum += part[(size_t)(s * ntiles + tile) * 8192 + idx];
        sum += bias[idx & 63];
        sum = (sum > 0.f) ? sum : 0.01f * sum;
        actT[(idx & 63) * 132 + (idx >> 6)] = sum;
    }
    __syncthreads();

    if (t < 128) {
        int m = t;
        float lg[NREL];
#pragma unroll
        for (int c = 0; c < NREL; c++) {
            float ssum = sm_b[c];
#pragma unroll 8
            for (int e = 0; e < 64; e++) ssum += actT[e * 132 + m] * sm_w[c * 64 + e];
            lg[c] = ssum;
        }
        float mx = lg[0];
#pragma unroll
        for (int c = 1; c < NREL; c++) mx = fmaxf(mx, lg[c]);
        float sum = 0.f;
#pragma unroll
        for (int c = 0; c < NREL; c++) { lg[c] = expf(lg[c] - mx); sum += lg[c]; }
        float inv = 1.f / sum;
#pragma unroll
        for (int c = 0; c < NREL; c++) out[(tile * 128 + m) * NREL + c] = lg[c] * inv;
    }
}

// -------- launcher --------
extern "C" void kernel_launch(void* const* d_in, const int* in_sizes, int n_in,
                              void* d_out, int out_size) {
    (void)in_sizes; (void)n_in; (void)out_size;
    const int*   left   = (const int*)d_in[0];
    const int*   right  = (const int*)d_in[1];
    const float* voc_w  = (const float*)d_in[2];
    const float* voc_b  = (const float*)d_in[3];
    const float* cps_w  = (const float*)d_in[4];
    const float* cps_b  = (const float*)d_in[5];
    const float* cpst_w = (const float*)d_in[6];
    const float* cpst_b = (const float*)d_in[7];
    const float* cpr_w  = (const float*)d_in[8];
    const float* cpr_b  = (const float*)d_in[9];
    const float* cprt_w = (const float*)d_in[10];
    const float* cprt_b = (const float*)d_in[11];
    const float* sm_w   = (const float*)d_in[12];
    const float* sm_b   = (const float*)d_in[13];
    float* out = (float*)d_out;

    float *XA, *XB, *Wc, *Wf, *bc, *bf, *part;
    cudaGetSymbolAddress((void**)&XA, g_XA);
    cudaGetSymbolAddress((void**)&XB, g_XB);
    cudaGetSymbolAddress((void**)&Wc, g_Wc);
    cudaGetSymbolAddress((void**)&Wf, g_Wf);
    cudaGetSymbolAddress((void**)&bc, g_bc);
    cudaGetSymbolAddress((void**)&bf, g_bf);
    cudaGetSymbolAddress((void**)&part, g_part);

    const int SMEM = (2 * 64 * PITCH + 64 * 128) * (int)sizeof(float);  // 98304 B
    cudaFuncSetAttribute(k_compose,    cudaFuncAttributeMaxDynamicSharedMemorySize, SMEM);
    cudaFuncSetAttribute(k_final_part, cudaFuncAttributeMaxDynamicSharedMemorySize, SMEM);

    k_transpose_voc<<<(VOC + 63) / 64, 256>>>(voc_w);
    k_prep<<<65 + (KTOT * D + 255) / 256, 256>>>(cps_w, cps_b, cpst_w, cpst_b,
                                                 cpr_w, cpr_b, cprt_w, cprt_b);
    k_embed<<<(2 * BATCH * NLEAVES * 16) / 256, 256>>>(left, right, voc_b);

    // levels 1..3: enough tiles, no split
    k_compose<<<512, 256, SMEM>>>(XA, XB, part, Wc, bc, 32, 1, 512);
    k_compose<<<256, 256, SMEM>>>(XB, XA, part, Wc, bc, 16, 1, 256);
    k_compose<<<128, 256, SMEM>>>(XA, XB, part, Wc, bc, 8, 1, 128);
    // level 4: 64 tiles, split 2
    k_compose<<<128, 256, SMEM>>>(XB, XA, part, Wc, bc, 4, 2, 64);
    k_reduce<<<64, 256>>>(part, XA, bc, 64, 2);
    // level 5: 32 tiles, split 4
    k_compose<<<128, 256, SMEM>>>(XA, XB, part, Wc, bc, 2, 4, 32);
    k_reduce<<<32, 256>>>(part, XB, bc, 32, 4);
    // level 6: 16 tiles, split 8
    k_compose<<<128, 256, SMEM>>>(XB, XA, part, Wc, bc, 1, 8, 16);
    k_reduce<<<16, 256>>>(part, XA, bc, 16, 8);
    // final: 8 tiles, split 16
    k_final_part<<<128, 256, SMEM>>>(XA, part, Wf, 16);
    k_final_reduce<<<BATCH / 128, 256>>>(part, out, bf, sm_w, sm_b, 16);
}

// round 5
// speedup vs baseline: 2.7375x; 2.7375x over previous
#include <cuda_runtime.h>
#include <math.h>
#include <cstdint>

#define BATCH 1024
#define D     64
#define VOC   50000
#define NREL  7
#define KC    2240      // folded compose K: 2080 tri + 128 linear + 32 pad
#define NCHC  70
#define KF    4224      // final K: 4096 kron + 128 linear
#define NCHF  132

#define APITCH 36       // A staging pitch (floats)
#define WPITCH 72       // W staging pitch (floats)

// shared-memory byte offsets
#define SO_IDX 16          // 2 x 128 B idx staging
#define SO_T   1024        // T[130][128] f32 = 66560 B
#define SO_A   67584       // A tile 128 x APITCH f32 = 18432 B
#define SO_W   86016       // W chunks, 2 x 32 x WPITCH f32 = 18432 B
#define SMEM_BYTES 104448

// -------- device scratch --------
__device__ float g_vocT[VOC * D];
__device__ float g_XA[2 * BATCH * 64 * D];
__device__ float g_XB[2 * BATCH * 32 * D];
__device__ float g_Wc2[NCHC * 2048];   // tf32 compose W chunks [c][k*64+e]
__device__ float g_Wf2[NCHF * 2048];   // tf32 final W chunks
__device__ int   g_idxC[KC];
__device__ int   g_idxF[KF];
__device__ float g_bc[D];
__device__ float g_bf[D];
__device__ float g_part[160 * 8192];   // K-split partials

// -------- PTX helpers --------
__device__ __forceinline__ uint32_t s2u(const void* p) {
    uint32_t a;
    asm("{.reg .u64 t; cvta.to.shared.u64 t, %1; cvt.u32.u64 %0, t;}" : "=r"(a) : "l"(p));
    return a;
}
__device__ __forceinline__ float cvt_tf32(float v) {
    float o;
    asm("cvt.rna.tf32.f32 %0, %1;" : "=f"(o) : "f"(v));
    return o;
}
__device__ __forceinline__ void mma8(float* d, const uint32_t* a, uint32_t b0, uint32_t b1) {
    asm volatile(
        "mma.sync.aligned.m16n8k8.row.col.f32.tf32.tf32.f32 "
        "{%0,%1,%2,%3},{%4,%5,%6,%7},{%8,%9},{%0,%1,%2,%3};"
        : "+f"(d[0]), "+f"(d[1]), "+f"(d[2]), "+f"(d[3])
        : "r"(a[0]), "r"(a[1]), "r"(a[2]), "r"(a[3]), "r"(b0), "r"(b1));
}
#define CPA16(dst, src) \
    asm volatile("cp.async.ca.shared.global [%0], [%1], 16;" :: "r"(dst), "l"(src))

// -------- vocab transpose --------
__global__ void k_transpose_voc(const float* __restrict__ voc_w) {
    __shared__ float tile[64][65];
    int v0 = blockIdx.x * 64;
    for (int idx = threadIdx.x; idx < 64 * 64; idx += 256) {
        int d = idx >> 6, vv = idx & 63;
        int v = v0 + vv;
        tile[vv][d] = (v < VOC) ? voc_w[d * VOC + v] : 0.f;
    }
    __syncthreads();
    for (int idx = threadIdx.x; idx < 64 * 64; idx += 256) {
        int vv = idx >> 6, d = idx & 63;
        int v = v0 + vv;
        if (v < VOC) g_vocT[v * D + d] = tile[vv][d];
    }
}

// -------- embedding gather --------
__global__ void k_embed(const int* __restrict__ left, const int* __restrict__ right,
                        const float* __restrict__ voc_b) {
    int t = blockIdx.x * 256 + threadIdx.x;
    int node = t >> 4;
    int c = (t & 15) * 4;
    int tree = node >> 16;
    int bl = node & 0xFFFF;
    int idx = tree ? right[bl] : left[bl];
    float4 v  = *(const float4*)(g_vocT + idx * D + c);
    float4 bb = *(const float4*)(voc_b + c);
    v.x += bb.x; v.y += bb.y; v.z += bb.z; v.w += bb.w;
    *(float4*)(g_XA + node * D + c) = v;
}

// -------- weight/index prep --------
__device__ __forceinline__ int tri_i_of_k(int k) {
    int i = (int)floorf((sqrtf(8.f * (float)k + 1.f) - 1.f) * 0.5f);
    while ((i + 1) * (i + 2) / 2 <= k) i++;
    while (i * (i + 1) / 2 > k) i--;
    return i;
}
__global__ void k_prep(const float* __restrict__ cps_w,  const float* __restrict__ cps_b,
                       const float* __restrict__ cpst_w, const float* __restrict__ cpst_b,
                       const float* __restrict__ cpr_w,  const float* __restrict__ cpr_b,
                       const float* __restrict__ cprt_w, const float* __restrict__ cprt_b) {
    int blk = blockIdx.x, t = threadIdx.x;
    if (blk < NCHC) {                       // compose W chunks (folded, tf32) [k][e]
        int c = blk;
        for (int u = t; u < 2048; u += 256) {
            int e = u & 63, kk = u >> 6;
            int k = c * 32 + kk;
            float v = 0.f;
            if (k < 2080) {
                int i = tri_i_of_k(k);
                int j = k - i * (i + 1) / 2;
                v = (j < i) ? cpst_w[e * 4096 + i * 64 + j] + cpst_w[e * 4096 + j * 64 + i]
                            : cpst_w[e * 4096 + i * 65];
            } else if (k < 2208) {
                v = cps_w[e * 128 + (k - 2080)];
            }
            g_Wc2[c * 2048 + u] = cvt_tf32(v);
        }
    } else if (blk < NCHC + NCHF) {         // final W chunks
        int c = blk - NCHC;
        for (int u = t; u < 2048; u += 256) {
            int e = u & 63, kk = u >> 6;
            int k = c * 32 + kk;
            float v = (k < 4096) ? cprt_w[e * 4096 + k] : cpr_w[e * 128 + (k - 4096)];
            g_Wf2[c * 2048 + u] = cvt_tf32(v);
        }
    } else if (blk == NCHC + NCHF) {        // biases
        if (t < D) {
            g_bc[t] = cps_b[t] + cpst_b[t];
            g_bf[t] = cpr_b[t] + cprt_b[t];
        }
    } else if (blk == NCHC + NCHF + 1) {    // compose idx
        for (int k = t; k < KC; k += 256) {
            int a, b2;
            if (k < 2080) { int i = tri_i_of_k(k); a = i; b2 = k - i * (i + 1) / 2; }
            else if (k < 2208) { a = k - 2080; b2 = 128; }   // linear: * ones row
            else { a = 129; b2 = 129; }                      // pad: zeros*zeros
            g_idxC[k] = a | (b2 << 8);
        }
    } else {                                // final idx
        for (int k = t; k < KF; k += 256) {
            int a, b2;
            if (k < 4096) { a = k >> 6; b2 = 64 + (k & 63); }  // l_i * r_j
            else { a = k - 4096; b2 = 128; }
            g_idxF[k] = a | (b2 << 8);
        }
    }
}

// -------- generic tensor-GEMM level (compose or final), register accumulators --------
__global__ void __launch_bounds__(256, 2) k_gemm(const float* __restrict__ Xin,
                                                 float* __restrict__ Xout,
                                                 float* __restrict__ part,
                                                 const float* __restrict__ Wq,
                                                 const int* __restrict__ idx,
                                                 const float* __restrict__ bias,
                                                 int n_out, int nchunks, int split,
                                                 int ntiles, int is_final) {
    extern __shared__ char smem[];
    const uint32_t sbase = s2u(smem);
    float* T  = (float*)(smem + SO_T);
    float* As = (float*)(smem + SO_A);
    const int t = threadIdx.x;
    const int s = blockIdx.x % split;
    const int tile = blockIdx.x / split;
    const int cpb = nchunks / split;      // splits divide evenly
    const int c0 = s * cpb, c1 = c0 + cpb;

    // stage chunk c0 (W 8KB -> [k][WPITCH], idx 128B)
    {
#pragma unroll
        for (int h = 0; h < 2; h++) {
            int u = t + h * 256;
            int k = u >> 4, e4 = (u & 15) * 4;
            CPA16(sbase + SO_W + (uint32_t)(k * WPITCH + e4) * 4,
                  Wq + (size_t)c0 * 2048 + u * 4);
        }
        if (t < 8) CPA16(sbase + SO_IDX + t * 16, idx + c0 * 32 + t * 4);
        asm volatile("cp.async.commit_group;");
    }

    // load L/R into T (transposed [feature][m]), plus ones/zeros rows
    {
        int m = t >> 1, half = t & 1;
        const float* src;
        if (is_final) {
            src = Xin + (size_t)(half * BATCH + tile * 128 + m) * D;
        } else {
            int g = tile * 128 + m;
            int p = g % n_out, bp = g / n_out;
            src = Xin + (size_t)(bp * 2 * n_out + 2 * p + half) * D;
        }
        float* dT = T + (half * 64) * 128 + m;
#pragma unroll
        for (int it = 0; it < 16; it++) {
            int f = it * 4;
            float4 v = *(const float4*)(src + f);
            dT[f * 128] = v.x; dT[(f + 1) * 128] = v.y;
            dT[(f + 2) * 128] = v.z; dT[(f + 3) * 128] = v.w;
        }
        if (t < 128) { T[128 * 128 + t] = 1.f; T[129 * 128 + t] = 0.f; }
    }

    const int l  = t & 31, wid = t >> 5;
    const int qr = l >> 2, qc = l & 3;        // l/4, l%4
    const int m0 = (wid & 3) * 32;            // warp M origin
    const int n0 = (wid >> 2) * 32;           // warp N origin
    const int mloc = t & 127;
    const int kh = (t >> 7) * 16;
    const float* Tm = T + mloc;
    float* Arow = As + mloc * APITCH + kh;

    float acc[2][4][4] = {};                  // [mfrag][nfrag][4]

    for (int c = c0; c < c1; c++) {
        int b = (c - c0) & 1;
        asm volatile("cp.async.wait_group 0;" ::: "memory");
        __syncthreads();    // W(c), idx(c) visible; prev frag loads done; T ready (1st iter)

        if (c + 1 < c1) {   // stage next chunk into other buffer
            int nb = b ^ 1;
#pragma unroll
            for (int h = 0; h < 2; h++) {
                int u = t + h * 256;
                int k = u >> 4, e4 = (u & 15) * 4;
                CPA16(sbase + SO_W + (uint32_t)(nb * 32 * WPITCH * 4 + (k * WPITCH + e4) * 4),
                      Wq + (size_t)(c + 1) * 2048 + u * 4);
            }
            if (t < 8) CPA16(sbase + SO_IDX + nb * 128 + t * 16, idx + (c + 1) * 32 + t * 4);
            asm volatile("cp.async.commit_group;");
        }

        // A-gen: 16 features per thread -> As[m][k], tf32
        {
            const int* ix = (const int*)(smem + SO_IDX + b * 128) + kh;
#pragma unroll
            for (int q = 0; q < 4; q++) {
                int p0 = ix[q * 4 + 0], p1 = ix[q * 4 + 1];
                int p2 = ix[q * 4 + 2], p3 = ix[q * 4 + 3];
                float4 v;
                v.x = cvt_tf32(Tm[(p0 & 255) * 128] * Tm[(p0 >> 8) * 128]);
                v.y = cvt_tf32(Tm[(p1 & 255) * 128] * Tm[(p1 >> 8) * 128]);
                v.z = cvt_tf32(Tm[(p2 & 255) * 128] * Tm[(p2 >> 8) * 128]);
                v.w = cvt_tf32(Tm[(p3 & 255) * 128] * Tm[(p3 >> 8) * 128]);
                *(float4*)(Arow + q * 4) = v;
            }
        }
        __syncthreads();

        // fragment loads + 32 HMMA
        const float* Wb = (const float*)(smem + SO_W) + b * (32 * WPITCH);
#pragma unroll
        for (int ks = 0; ks < 4; ks++) {
            int k0 = ks * 8;
            uint32_t af[2][4];
#pragma unroll
            for (int mf = 0; mf < 2; mf++) {
                const uint32_t* ap =
                    (const uint32_t*)(As + (m0 + mf * 16 + qr) * APITCH + k0 + qc);
                af[mf][0] = ap[0];
                af[mf][1] = ap[8 * APITCH];
                af[mf][2] = ap[4];
                af[mf][3] = ap[8 * APITCH + 4];
            }
#pragma unroll
            for (int nf = 0; nf < 4; nf++) {
                const uint32_t* bp =
                    (const uint32_t*)(Wb + (k0 + qc) * WPITCH + n0 + nf * 8 + qr);
                uint32_t b0 = bp[0], b1 = bp[4 * WPITCH];
                mma8(acc[0][nf], af[0], b0, b1);
                mma8(acc[1][nf], af[1], b0, b1);
            }
        }
    }

    // epilogue: registers -> global
#pragma unroll
    for (int mf = 0; mf < 2; mf++) {
#pragma unroll
        for (int nf = 0; nf < 4; nf++) {
            int row = m0 + mf * 16 + qr;
            int col = n0 + nf * 8 + qc * 2;
            float* a4 = acc[mf][nf];
            if (split == 1) {
                float b0v = __ldg(bias + col), b1v = __ldg(bias + col + 1);
                float* dst = Xout + (size_t)(tile * 128 + row) * D + col;
                *(float2*)dst = make_float2(tanhf(a4[0] + b0v), tanhf(a4[1] + b1v));
                dst += 8 * D;
                *(float2*)dst = make_float2(tanhf(a4[2] + b0v), tanhf(a4[3] + b1v));
            } else {
                float* dst = part + (size_t)(s * ntiles + tile) * 8192 + row * 64 + col;
                *(float2*)dst = make_float2(a4[0], a4[1]);
                *(float2*)(dst + 8 * 64) = make_float2(a4[2], a4[3]);
            }
        }
    }
}

// -------- sum K-split partials + bias + tanh --------
__global__ void __launch_bounds__(256) k_reduce(const float* __restrict__ part,
                                                float* __restrict__ Xout,
                                                const float* __restrict__ bias,
                                                int ntiles, int split) {
    int tile = blockIdx.x;
    for (int idx = threadIdx.x; idx < 8192; idx += 256) {
        float sum = 0.f;
        for (int s = 0; s < split; s++) sum += part[(size_t)(s * ntiles + tile) * 8192 + idx];
        Xout[(size_t)tile * 8192 + idx] = tanhf(sum + bias[idx & 63]);
    }
}

// -------- final epilogue: reduce + bias + leaky + logits + softmax --------
__global__ void __launch_bounds__(256) k_final_reduce(const float* __restrict__ part,
                                                      float* __restrict__ out,
                                                      const float* __restrict__ bias,
                                                      const float* __restrict__ sm_w,
                                                      const float* __restrict__ sm_b,
                                                      int split) {
    __shared__ float actT[64 * 132];
    const int tile = blockIdx.x;
    const int t = threadIdx.x;
    const int ntiles = BATCH / 128;

    for (int idx = t; idx < 8192; idx += 256) {
        float sum = 0.f;
        for (int s = 0; s < split; s++) sum += part[(size_t)(s * ntiles + tile) * 8192 + idx];
        sum += bias[idx & 63];
        sum = (sum > 0.f) ? sum : 0.01f * sum;
        actT[(idx & 63) * 132 + (idx >> 6)] = sum;
    }
    __syncthreads();

    if (t < 128) {
        int m = t;
        float lg[NREL];
#pragma unroll
        for (int c = 0; c < NREL; c++) {
            float ssum = sm_b[c];
#pragma unroll 8
            for (int e = 0; e < 64; e++) ssum += actT[e * 132 + m] * sm_w[c * 64 + e];
            lg[c] = ssum;
        }
        float mx = lg[0];
#pragma unroll
        for (int c = 1; c < NREL; c++) mx = fmaxf(mx, lg[c]);
        float sum = 0.f;
#pragma unroll
        for (int c = 0; c < NREL; c++) { lg[c] = expf(lg[c] - mx); sum += lg[c]; }
        float inv = 1.f / sum;
#pragma unroll
        for (int c = 0; c < NREL; c++) out[(tile * 128 + m) * NREL + c] = lg[c] * inv;
    }
}

// -------- launcher --------
extern "C" void kernel_launch(void* const* d_in, const int* in_sizes, int n_in,
                              void* d_out, int out_size) {
    (void)in_sizes; (void)n_in; (void)out_size;
    const int*   left   = (const int*)d_in[0];
    const int*   right  = (const int*)d_in[1];
    const float* voc_w  = (const float*)d_in[2];
    const float* voc_b  = (const float*)d_in[3];
    const float* cps_w  = (const float*)d_in[4];
    const float* cps_b  = (const float*)d_in[5];
    const float* cpst_w = (const float*)d_in[6];
    const float* cpst_b = (const float*)d_in[7];
    const float* cpr_w  = (const float*)d_in[8];
    const float* cpr_b  = (const float*)d_in[9];
    const float* cprt_w = (const float*)d_in[10];
    const float* cprt_b = (const float*)d_in[11];
    const float* sm_w   = (const float*)d_in[12];
    const float* sm_b   = (const float*)d_in[13];
    float* out = (float*)d_out;

    float *XA, *XB, *Wc2, *Wf2, *bc, *bf, *part;
    int *idxC, *idxF;
    cudaGetSymbolAddress((void**)&XA, g_XA);
    cudaGetSymbolAddress((void**)&XB, g_XB);
    cudaGetSymbolAddress((void**)&Wc2, g_Wc2);
    cudaGetSymbolAddress((void**)&Wf2, g_Wf2);
    cudaGetSymbolAddress((void**)&bc, g_bc);
    cudaGetSymbolAddress((void**)&bf, g_bf);
    cudaGetSymbolAddress((void**)&part, g_part);
    cudaGetSymbolAddress((void**)&idxC, g_idxC);
    cudaGetSymbolAddress((void**)&idxF, g_idxF);

    cudaFuncSetAttribute(k_gemm, cudaFuncAttributeMaxDynamicSharedMemorySize, SMEM_BYTES);

    k_transpose_voc<<<(VOC + 63) / 64, 256>>>(voc_w);
    k_prep<<<NCHC + NCHF + 3, 256>>>(cps_w, cps_b, cpst_w, cpst_b,
                                     cpr_w, cpr_b, cprt_w, cprt_b);
    k_embed<<<(2 * BATCH * 64 * 16) / 256, 256>>>(left, right, voc_b);

    // levels 1..3: no split, fused tanh
    k_gemm<<<512, 256, SMEM_BYTES>>>(XA, XB, part, Wc2, idxC, bc, 32, NCHC, 1, 512, 0);
    k_gemm<<<256, 256, SMEM_BYTES>>>(XB, XA, part, Wc2, idxC, bc, 16, NCHC, 1, 256, 0);
    k_gemm<<<128, 256, SMEM_BYTES>>>(XA, XB, part, Wc2, idxC, bc,  8, NCHC, 1, 128, 0);
    // level 4: 64 tiles, split 2
    k_gemm<<<128, 256, SMEM_BYTES>>>(XB, XA, part, Wc2, idxC, bc,  4, NCHC, 2,  64, 0);
    k_reduce<<<64, 256>>>(part, XA, bc, 64, 2);
    // level 5: 32 tiles, split 5
    k_gemm<<<160, 256, SMEM_BYTES>>>(XA, XB, part, Wc2, idxC, bc,  2, NCHC, 5,  32, 0);
    k_reduce<<<32, 256>>>(part, XB, bc, 32, 5);
    // level 6: 16 tiles, split 7
    k_gemm<<<112, 256, SMEM_BYTES>>>(XB, XA, part, Wc2, idxC, bc,  1, NCHC, 7,  16, 0);
    k_reduce<<<16, 256>>>(part, XA, bc, 16, 7);
    // final: 8 tiles, split 12
    k_gemm<<<96, 256, SMEM_BYTES>>>(XA, XB, part, Wf2, idxF, bf, 1, NCHF, 12, 8, 1);
    k_final_reduce<<<BATCH / 128, 256>>>(part, out, bf, sm_w, sm_b, 12);
}